// round 1
// baseline (speedup 1.0000x reference)
#include <cuda_runtime.h>
#include <cuda_bf16.h>
#include <math.h>

// ---------------------------------------------------------------------------
// MLPAttention fused pipeline, fp32 baseline.
// B=32, S=2048, D=1024.
// out layout: [0,32768) h_tilde | [32768,65536) weighted_context | [65536,131072) attn_w
// ---------------------------------------------------------------------------

#define B_SZ   32
#define S_SZ   2048
#define D_SZ   1024
#define R_SZ   (B_SZ * S_SZ)        // 65536 rows of the big GEMM
#define NDT    8                    // number of 128-wide d tiles (1024/128)

// Scratch (static device arrays: no allocation allowed)
__device__ float g_target[B_SZ * D_SZ];          // input @ W_in^T + b_c  (32x1024)
__device__ float g_part[NDT * R_SZ];             // partial scores per d-tile (8 x 65536)

// ---------------------------------------------------------------------------
// Kernel 1: target[b,e] = sum_k input[b,k] * W_in[e,k] + b_c[e]
// grid (8, 32): blockIdx.x = 128-wide e chunk, blockIdx.y = b. 128 threads.
// ---------------------------------------------------------------------------
__global__ __launch_bounds__(128) void target_kernel(
    const float* __restrict__ input,
    const float* __restrict__ W_in,
    const float* __restrict__ b_c)
{
    __shared__ float x_s[D_SZ];
    __shared__ float Ws[128][33];
    const int tid   = threadIdx.x;
    const int chunk = blockIdx.x;
    const int b     = blockIdx.y;

    for (int i = tid; i < D_SZ; i += 128)
        x_s[i] = input[b * D_SZ + i];

    const int row = chunk * 128 + tid;   // e index
    float acc = 0.f;

    for (int k0 = 0; k0 < D_SZ; k0 += 32) {
        __syncthreads();
        for (int i = tid; i < 128 * 32; i += 128) {
            int d = i >> 5, k = i & 31;
            Ws[d][k] = W_in[(chunk * 128 + d) * D_SZ + k0 + k];
        }
        __syncthreads();
        #pragma unroll
        for (int k = 0; k < 32; k++)
            acc += x_s[k0 + k] * Ws[tid][k];
    }
    g_target[b * D_SZ + row] = acc + b_c[row];
}

// ---------------------------------------------------------------------------
// Kernel 2 (dominant): fused GEMM + tanh + W_v reduction.
//   y[r, e] = sum_k context[r, k] * W_c[e, k]       (r = b*2048+s)
//   part[dt, r] = sum_{e in tile dt} W_v[e] * tanh(target[b,e] + y[r,e])
// 128x128x16 tile, 256 threads, 8x8 register tile.
// grid (8 d-tiles [x, inner for L2 reuse of context], 512 r-tiles [y]).
// ---------------------------------------------------------------------------
__global__ __launch_bounds__(256, 2) void score_kernel(
    const float* __restrict__ A,      // context  (R_SZ x 1024)
    const float* __restrict__ Wc,     // (1024 x 1024)
    const float* __restrict__ Wv)     // (1024)
{
    __shared__ float As[16][128];
    __shared__ float Bs[16][128];
    __shared__ float tgt_s[128];
    __shared__ float wv_s[128];

    const int tid = threadIdx.x;
    const int d0  = blockIdx.x * 128;
    const int r0  = blockIdx.y * 128;
    const int b   = r0 >> 11;                 // r0 / 2048 (tiles never straddle b)

    if (tid < 128) tgt_s[tid] = g_target[b * D_SZ + d0 + tid];
    else           wv_s[tid - 128] = Wv[d0 + (tid - 128)];

    float c[8][8];
    #pragma unroll
    for (int i = 0; i < 8; i++)
        #pragma unroll
        for (int j = 0; j < 8; j++) c[i][j] = 0.f;

    const float* Aptr = A  + (size_t)r0 * D_SZ;
    const float* Bptr = Wc + (size_t)d0 * D_SZ;

    const int lr = tid >> 2;          // 0..63
    const int lk = (tid & 3) * 4;     // 0,4,8,12
    const int ty = tid >> 4;          // 0..15 -> rows ty*8..ty*8+7
    const int tx = tid & 15;          // 0..15 -> cols tx*8..tx*8+7

    for (int k0 = 0; k0 < D_SZ; k0 += 16) {
        float4 a0 = *(const float4*)(Aptr + (size_t)lr * D_SZ + k0 + lk);
        float4 a1 = *(const float4*)(Aptr + (size_t)(lr + 64) * D_SZ + k0 + lk);
        float4 b0 = *(const float4*)(Bptr + (size_t)lr * D_SZ + k0 + lk);
        float4 b1 = *(const float4*)(Bptr + (size_t)(lr + 64) * D_SZ + k0 + lk);

        __syncthreads();
        As[lk + 0][lr] = a0.x; As[lk + 1][lr] = a0.y;
        As[lk + 2][lr] = a0.z; As[lk + 3][lr] = a0.w;
        As[lk + 0][lr + 64] = a1.x; As[lk + 1][lr + 64] = a1.y;
        As[lk + 2][lr + 64] = a1.z; As[lk + 3][lr + 64] = a1.w;
        Bs[lk + 0][lr] = b0.x; Bs[lk + 1][lr] = b0.y;
        Bs[lk + 2][lr] = b0.z; Bs[lk + 3][lr] = b0.w;
        Bs[lk + 0][lr + 64] = b1.x; Bs[lk + 1][lr + 64] = b1.y;
        Bs[lk + 2][lr + 64] = b1.z; Bs[lk + 3][lr + 64] = b1.w;
        __syncthreads();

        #pragma unroll
        for (int k = 0; k < 16; k++) {
            float ar[8], br[8];
            *(float4*)&ar[0] = *(const float4*)&As[k][ty * 8];
            *(float4*)&ar[4] = *(const float4*)&As[k][ty * 8 + 4];
            *(float4*)&br[0] = *(const float4*)&Bs[k][tx * 8];
            *(float4*)&br[4] = *(const float4*)&Bs[k][tx * 8 + 4];
            #pragma unroll
            for (int i = 0; i < 8; i++)
                #pragma unroll
                for (int j = 0; j < 8; j++)
                    c[i][j] += ar[i] * br[j];
        }
    }

    // Epilogue: tanh + W_v dot over this d-tile, reduce across tx (16 lanes).
    float wv[8], tg[8];
    #pragma unroll
    for (int j = 0; j < 8; j++) {
        wv[j] = wv_s[tx * 8 + j];
        tg[j] = tgt_s[tx * 8 + j];
    }

    #pragma unroll
    for (int i = 0; i < 8; i++) {
        float p = 0.f;
        #pragma unroll
        for (int j = 0; j < 8; j++)
            p += wv[j] * tanhf(tg[j] + c[i][j]);
        // reduce within 16-lane segments (same ty, tx 0..15)
        #pragma unroll
        for (int off = 8; off > 0; off >>= 1)
            p += __shfl_down_sync(0xffffffffu, p, off, 16);
        if (tx == 0)
            g_part[(size_t)blockIdx.x * R_SZ + r0 + ty * 8 + i] = p;
    }
}

// ---------------------------------------------------------------------------
// Kernel 3: softmax over S per batch; also zero the weighted_context region.
// grid (32), 256 threads; each thread owns 8 of the 2048 elements.
// ---------------------------------------------------------------------------
__global__ __launch_bounds__(256) void softmax_kernel(float* __restrict__ out)
{
    const int b   = blockIdx.x;
    const int tid = threadIdx.x;
    __shared__ float red[256];

    // zero wc region (written next kernel)
    for (int i = tid; i < D_SZ; i += 256)
        out[32768 + b * D_SZ + i] = 0.f;

    float v[8];
    float mx = -1e30f;
    #pragma unroll
    for (int j = 0; j < 8; j++) {
        const int idx = b * S_SZ + j * 256 + tid;
        float s = 0.f;
        #pragma unroll
        for (int t = 0; t < NDT; t++)
            s += g_part[(size_t)t * R_SZ + idx];
        v[j] = s;
        mx = fmaxf(mx, s);
    }
    red[tid] = mx; __syncthreads();
    for (int s = 128; s > 0; s >>= 1) {
        if (tid < s) red[tid] = fmaxf(red[tid], red[tid + s]);
        __syncthreads();
    }
    mx = red[0];
    __syncthreads();

    float sum = 0.f;
    #pragma unroll
    for (int j = 0; j < 8; j++) {
        v[j] = expf(v[j] - mx);
        sum += v[j];
    }
    red[tid] = sum; __syncthreads();
    for (int s = 128; s > 0; s >>= 1) {
        if (tid < s) red[tid] += red[tid + s];
        __syncthreads();
    }
    const float inv = 1.f / red[0];

    #pragma unroll
    for (int j = 0; j < 8; j++)
        out[65536 + b * S_SZ + j * 256 + tid] = v[j] * inv;
}

// ---------------------------------------------------------------------------
// Kernel 4: weighted_context[b,d] = sum_s attn_w[b,s] * context[b,s,d]
// grid (32 b, 4 d-chunks), 256 threads: thread owns one d, loops all S.
// Coalesced over d at each s. Deterministic (no split-s atomics).
// ---------------------------------------------------------------------------
__global__ __launch_bounds__(256) void wctx_kernel(
    const float* __restrict__ context,
    float* __restrict__ out)
{
    const int b   = blockIdx.x;
    const int tid = threadIdx.x;
    const int d   = blockIdx.y * 256 + tid;

    const float* w = out + 65536 + b * S_SZ;
    const float* C = context + (size_t)b * S_SZ * D_SZ + d;

    float acc = 0.f;
    #pragma unroll 8
    for (int s = 0; s < S_SZ; s++)
        acc += w[s] * C[(size_t)s * D_SZ];

    out[32768 + b * D_SZ + d] = acc;
}

// ---------------------------------------------------------------------------
// Kernel 5: h_tilde[b,e] = tanh( sum_{k<2048} cat[b,k] * W_out[e,k] )
//           cat = [weighted_context, input]
// grid (8, 32), 128 threads. Same smem-tiled GEMV pattern as kernel 1.
// ---------------------------------------------------------------------------
__global__ __launch_bounds__(128) void htilde_kernel(
    const float* __restrict__ input,
    const float* __restrict__ W_out,
    float* __restrict__ out)
{
    __shared__ float x_s[2 * D_SZ];
    __shared__ float Ws[128][33];
    const int tid   = threadIdx.x;
    const int chunk = blockIdx.x;
    const int b     = blockIdx.y;

    for (int i = tid; i < 2 * D_SZ; i += 128)
        x_s[i] = (i < D_SZ) ? out[32768 + b * D_SZ + i]
                            : input[b * D_SZ + (i - D_SZ)];

    const int row = chunk * 128 + tid;   // e index
    float acc = 0.f;

    for (int k0 = 0; k0 < 2 * D_SZ; k0 += 32) {
        __syncthreads();
        for (int i = tid; i < 128 * 32; i += 128) {
            int d = i >> 5, k = i & 31;
            Ws[d][k] = W_out[(size_t)(chunk * 128 + d) * (2 * D_SZ) + k0 + k];
        }
        __syncthreads();
        #pragma unroll
        for (int k = 0; k < 32; k++)
            acc += x_s[k0 + k] * Ws[tid][k];
    }
    out[b * D_SZ + row] = tanhf(acc);
}

// ---------------------------------------------------------------------------
extern "C" void kernel_launch(void* const* d_in, const int* in_sizes, int n_in,
                              void* d_out, int out_size)
{
    const float* input   = (const float*)d_in[0];   // (32,1024)
    const float* context = (const float*)d_in[1];   // (32,2048,1024)
    const float* W_in    = (const float*)d_in[2];   // (1024,1024)
    const float* W_c     = (const float*)d_in[3];   // (1024,1024)
    const float* b_c     = (const float*)d_in[4];   // (1024)
    const float* W_v     = (const float*)d_in[5];   // (1024)
    const float* W_out   = (const float*)d_in[6];   // (1024,2048)
    float* out = (float*)d_out;

    target_kernel <<< dim3(8, 32),   128 >>> (input, W_in, b_c);
    score_kernel  <<< dim3(8, 512),  256 >>> (context, W_c, W_v);
    softmax_kernel<<< 32,            256 >>> (out);
    wctx_kernel   <<< dim3(32, 4),   256 >>> (context, out);
    htilde_kernel <<< dim3(8, 32),   128 >>> (input, W_out, out);
}

// round 3
// speedup vs baseline: 2.0995x; 2.0995x over previous
#include <cuda_runtime.h>
#include <cuda_bf16.h>
#include <math.h>
#include <cstdint>

// ---------------------------------------------------------------------------
// MLPAttention: mma.sync bf16-split pipeline (sm_100 base target, no tcgen05).
// B=32, S=2048, D=1024.
// out: [0,32768) h_tilde | [32768,65536) weighted_context | [65536,131072) attn_w
// ---------------------------------------------------------------------------

#define B_SZ   32
#define S_SZ   2048
#define D_SZ   1024
#define R_SZ   (B_SZ * S_SZ)

// Scratch (module statics: no runtime allocation)
__device__ float g_target[B_SZ * D_SZ];          // input @ W_in^T + b_c
__device__ float g_scores[R_SZ];                 // pre-softmax scores
__device__ float g_part[B_SZ * 8 * D_SZ];        // wctx split-S partials
// Fragment-ordered bf16 hi/lo planes.
// A (context): blocks [rt(512)][ks(64)][mt(8)] of [lane(32)]x16B
__device__ uint4 g_AH[(size_t)R_SZ * D_SZ / 8];  // 128MB
__device__ uint4 g_AL[(size_t)R_SZ * D_SZ / 8];  // 128MB
// B (W_c): blocks [dc(8)][ks(64)][nt(16)] of [lane(32)]x8B
__device__ uint2 g_BH[(size_t)D_SZ * D_SZ / 4];  // 2MB
__device__ uint2 g_BL[(size_t)D_SZ * D_SZ / 4];  // 2MB

// ---------------------------------------------------------------------------
// helpers
// ---------------------------------------------------------------------------
__device__ __forceinline__ uint32_t smem_u32(const void* p) {
    uint32_t a;
    asm("{ .reg .u64 t; cvta.to.shared.u64 t, %1; cvt.u32.u64 %0, t; }" : "=r"(a) : "l"(p));
    return a;
}

// rn hi/lo split: (a,b) -> packed bf16x2 hi (lo16=a, hi16=b) and lo residuals
__device__ __forceinline__ uint32_t split2(float a, float b, uint32_t& lo) {
    uint32_t h;
    asm("cvt.rn.bf16x2.f32 %0, %1, %2;" : "=r"(h) : "f"(b), "f"(a));
    float ah = __uint_as_float(h << 16);
    float bh = __uint_as_float(h & 0xFFFF0000u);
    float al = a - ah, bl = b - bh;
    uint32_t l;
    asm("cvt.rn.bf16x2.f32 %0, %1, %2;" : "=r"(l) : "f"(bl), "f"(al));
    lo = l;
    return h;
}

#define MMA_BF16(c, a, b)                                                       \
    asm volatile("mma.sync.aligned.m16n8k16.row.col.f32.bf16.bf16.f32 "         \
        "{%0,%1,%2,%3}, {%4,%5,%6,%7}, {%8,%9}, {%0,%1,%2,%3};"                 \
        : "+f"((c)[0]), "+f"((c)[1]), "+f"((c)[2]), "+f"((c)[3])                \
        : "r"((a).x), "r"((a).y), "r"((a).z), "r"((a).w),                       \
          "r"((b).x), "r"((b).y))

#define CP16(d, s)                                                              \
    asm volatile("cp.async.cg.shared.global [%0], [%1], 16;"                    \
                 :: "r"(d), "l"(s) : "memory")

// ---------------------------------------------------------------------------
// Kernel 0a: split context into bf16 hi/lo planes in A-fragment order.
// One warp per (mtile(4096), ks(64)) pair; 32768 blocks x 256 threads.
// m16n8k16 A fragment, lane l: rows {l/4, l/4+8}, cols {(l%4)*2(+1), +8(+1)}.
// ---------------------------------------------------------------------------
__global__ __launch_bounds__(256) void prep_ctx_kernel(const float* __restrict__ ctx)
{
    const int task  = blockIdx.x * 8 + (threadIdx.x >> 5);
    const int lane  = threadIdx.x & 31;
    const int mtile = task >> 6;          // 0..4095 (16-row tiles)
    const int ks    = task & 63;          // 16-wide k step

    const int  r0 = mtile * 16 + (lane >> 2);
    const int  kb = ks * 16 + (lane & 3) * 2;
    const float* p0 = ctx + (size_t)r0 * D_SZ + kb;
    const float* p1 = ctx + (size_t)(r0 + 8) * D_SZ + kb;

    float2 f00 = *(const float2*)(p0);
    float2 f10 = *(const float2*)(p1);
    float2 f02 = *(const float2*)(p0 + 8);
    float2 f12 = *(const float2*)(p1 + 8);

    uint4 h, l;
    h.x = split2(f00.x, f00.y, l.x);   // a0,a1
    h.y = split2(f10.x, f10.y, l.y);   // a2,a3
    h.z = split2(f02.x, f02.y, l.z);   // a4,a5
    h.w = split2(f12.x, f12.y, l.w);   // a6,a7

    const int rt = mtile >> 3, mt = mtile & 7;
    const size_t blk = ((size_t)rt * 64 + ks) * 8 + mt;
    g_AH[blk * 32 + lane] = h;
    g_AL[blk * 32 + lane] = l;
}

// ---------------------------------------------------------------------------
// Kernel 0b: split W_c into bf16 hi/lo planes in B-fragment order.
// One warp per (ntile(128), ks(64)); 1024 blocks x 256 threads.
// B fragment (col), lane l: col n = l/4, rows(k) {(l%4)*2(+1), +8(+1)}.
// ---------------------------------------------------------------------------
__global__ __launch_bounds__(256) void prep_wc_kernel(const float* __restrict__ Wc)
{
    const int task  = blockIdx.x * 8 + (threadIdx.x >> 5);
    const int lane  = threadIdx.x & 31;
    const int ntile = task >> 6;          // 0..127 (8-col tiles)
    const int ks    = task & 63;

    const int n  = ntile * 8 + (lane >> 2);
    const int kb = ks * 16 + (lane & 3) * 2;
    float2 f0 = *(const float2*)(Wc + (size_t)n * D_SZ + kb);
    float2 f2 = *(const float2*)(Wc + (size_t)n * D_SZ + kb + 8);

    uint2 h, l;
    h.x = split2(f0.x, f0.y, l.x);     // b0,b1
    h.y = split2(f2.x, f2.y, l.y);     // b2,b3

    const int dc = ntile >> 4, nt = ntile & 15;
    const size_t blk = ((size_t)dc * 64 + ks) * 16 + nt;
    g_BH[blk * 32 + lane] = h;
    g_BL[blk * 32 + lane] = l;
}

// ---------------------------------------------------------------------------
// Kernel 1: target[b,e] = input[b,:] @ W_in[e,:] + b_c[e]
// ---------------------------------------------------------------------------
__global__ __launch_bounds__(128) void target_kernel(
    const float* __restrict__ input,
    const float* __restrict__ W_in,
    const float* __restrict__ b_c)
{
    __shared__ float x_s[D_SZ];
    __shared__ float Ws[128][33];
    const int tid = threadIdx.x, chunk = blockIdx.x, b = blockIdx.y;

    for (int i = tid; i < D_SZ; i += 128) x_s[i] = input[b * D_SZ + i];
    const int row = chunk * 128 + tid;
    float acc = 0.f;
    for (int k0 = 0; k0 < D_SZ; k0 += 32) {
        __syncthreads();
        for (int i = tid; i < 128 * 32; i += 128) {
            int d = i >> 5, k = i & 31;
            Ws[d][k] = W_in[(chunk * 128 + d) * D_SZ + k0 + k];
        }
        __syncthreads();
        #pragma unroll
        for (int k = 0; k < 32; k++) acc += x_s[k0 + k] * Ws[tid][k];
    }
    g_target[b * D_SZ + row] = acc + b_c[row];
}

// ---------------------------------------------------------------------------
// Kernel 2 (dominant): mma.sync bf16-split GEMM + tanh + W_v reduce -> scores.
// One CTA per 128 context rows (grid 512), 256 threads (8 warps).
// Warp grid 4(m) x 2(n): warp tile 32 x 64. d loop: 8 chunks of 128 cols.
// k pipeline: 32-wide k chunks, cp.async, 4 smem stages.
// ---------------------------------------------------------------------------
#define STAGES      4
#define STAGE_BYTES 32768            // AH 8K | AL 8K | BH 8K | BL 8K
#define TGT_OFF     (STAGES * STAGE_BYTES)
#define WV_OFF      (TGT_OFF + 4096)
#define SC_OFF      (WV_OFF + 4096)
#define SMEM_SCORE  (SC_OFF + 512)

__global__ __launch_bounds__(256, 1) void score_kernel(const float* __restrict__ Wv)
{
    extern __shared__ char smem[];
    const int tid  = threadIdx.x, wid = tid >> 5, lane = tid & 31;
    const int wm   = wid & 3, wn = wid >> 2;
    const int rt   = blockIdx.x;
    const int r0   = rt * 128, b = r0 >> 11;

    float* tgt_s = (float*)(smem + TGT_OFF);
    float* wv_s  = (float*)(smem + WV_OFF);
    float* sc_s  = (float*)(smem + SC_OFF);
    for (int i = tid; i < D_SZ; i += 256) {
        tgt_s[i] = g_target[b * D_SZ + i];
        wv_s[i]  = Wv[i];
    }

    const uint32_t sb = smem_u32(smem);

    // stage issue: copy 32KB (A 16K + B 16K) for iteration it
    auto issue = [&](int it) {
        const int kc = it & 31, dc = it >> 5, p = it & 3;
        const char* sAH = (const char*)g_AH + (size_t)(rt * 64 + kc * 2) * 4096;
        const char* sAL = (const char*)g_AL + (size_t)(rt * 64 + kc * 2) * 4096;
        const char* sBH = (const char*)g_BH + (size_t)(dc * 64 + kc * 2) * 4096;
        const char* sBL = (const char*)g_BL + (size_t)(dc * 64 + kc * 2) * 4096;
        const uint32_t d = sb + p * STAGE_BYTES + tid * 16;
        CP16(d + 0,            sAH + tid * 16);
        CP16(d + 4096,         sAH + tid * 16 + 4096);
        CP16(d + 8192,         sAL + tid * 16);
        CP16(d + 8192 + 4096,  sAL + tid * 16 + 4096);
        CP16(d + 16384,        sBH + tid * 16);
        CP16(d + 16384 + 4096, sBH + tid * 16 + 4096);
        CP16(d + 24576,        sBL + tid * 16);
        CP16(d + 24576 + 4096, sBL + tid * 16 + 4096);
        asm volatile("cp.async.commit_group;" ::: "memory");
    };

    issue(0); issue(1); issue(2);

    float c[2][8][4];
    float acc[2][2] = {{0.f, 0.f}, {0.f, 0.f}};

    for (int i = 0; i < 256; i++) {
        if ((i & 31) == 0) {
            #pragma unroll
            for (int m = 0; m < 2; m++)
                #pragma unroll
                for (int n = 0; n < 8; n++)
                    #pragma unroll
                    for (int q = 0; q < 4; q++) c[m][n][q] = 0.f;
        }

        if (i <= 253)      asm volatile("cp.async.wait_group 2;" ::: "memory");
        else if (i == 254) asm volatile("cp.async.wait_group 1;" ::: "memory");
        else               asm volatile("cp.async.wait_group 0;" ::: "memory");
        __syncthreads();
        if (i + 3 < 256) issue(i + 3);

        const char* st = smem + (i & 3) * STAGE_BYTES;
        #pragma unroll
        for (int ks = 0; ks < 2; ks++) {
            uint4 aH[2], aL[2];
            #pragma unroll
            for (int m = 0; m < 2; m++) {
                const int mt = wm * 2 + m;
                aH[m] = *(const uint4*)(st +        ((ks * 8 + mt) * 32 + lane) * 16);
                aL[m] = *(const uint4*)(st + 8192 + ((ks * 8 + mt) * 32 + lane) * 16);
            }
            #pragma unroll
            for (int n = 0; n < 8; n++) {
                const int nt = wn * 8 + n;
                uint2 bH = *(const uint2*)(st + 16384 + ((ks * 16 + nt) * 32 + lane) * 8);
                uint2 bL = *(const uint2*)(st + 24576 + ((ks * 16 + nt) * 32 + lane) * 8);
                #pragma unroll
                for (int m = 0; m < 2; m++) {
                    MMA_BF16(c[m][n], aH[m], bH);
                    MMA_BF16(c[m][n], aH[m], bL);
                    MMA_BF16(c[m][n], aL[m], bH);
                }
            }
        }

        if ((i & 31) == 31) {
            const int dc = i >> 5;
            const int d0 = dc * 128 + wn * 64;
            #pragma unroll
            for (int m = 0; m < 2; m++) {
                #pragma unroll
                for (int n = 0; n < 8; n++) {
                    const int col = d0 + n * 8 + (lane & 3) * 2;
                    const float w0 = wv_s[col], w1 = wv_s[col + 1];
                    const float t0 = tgt_s[col], t1 = tgt_s[col + 1];
                    acc[m][0] += w0 * tanhf(t0 + c[m][n][0]) + w1 * tanhf(t1 + c[m][n][1]);
                    acc[m][1] += w0 * tanhf(t0 + c[m][n][2]) + w1 * tanhf(t1 + c[m][n][3]);
                }
            }
        }
    }

    // reduce the 4 lanes sharing each output row (lane&3 = col group)
    #pragma unroll
    for (int m = 0; m < 2; m++)
        #pragma unroll
        for (int h = 0; h < 2; h++) {
            acc[m][h] += __shfl_xor_sync(0xffffffffu, acc[m][h], 1);
            acc[m][h] += __shfl_xor_sync(0xffffffffu, acc[m][h], 2);
        }

    if (wn == 0 && (lane & 3) == 0) {
        #pragma unroll
        for (int m = 0; m < 2; m++)
            #pragma unroll
            for (int h = 0; h < 2; h++)
                sc_s[wm * 32 + m * 16 + h * 8 + (lane >> 2)] = acc[m][h];
    }
    __syncthreads();
    if (wn == 1 && (lane & 3) == 0) {
        #pragma unroll
        for (int m = 0; m < 2; m++)
            #pragma unroll
            for (int h = 0; h < 2; h++)
                sc_s[wm * 32 + m * 16 + h * 8 + (lane >> 2)] += acc[m][h];
    }
    __syncthreads();
    if (tid < 128) g_scores[r0 + tid] = sc_s[tid];
}

// ---------------------------------------------------------------------------
// Kernel 3: softmax over S per batch.
// ---------------------------------------------------------------------------
__global__ __launch_bounds__(256) void softmax_kernel(float* __restrict__ out)
{
    const int b = blockIdx.x, tid = threadIdx.x;
    __shared__ float red[256];

    float v[8];
    float mx = -1e30f;
    #pragma unroll
    for (int j = 0; j < 8; j++) {
        v[j] = g_scores[b * S_SZ + j * 256 + tid];
        mx = fmaxf(mx, v[j]);
    }
    red[tid] = mx; __syncthreads();
    for (int s = 128; s > 0; s >>= 1) {
        if (tid < s) red[tid] = fmaxf(red[tid], red[tid + s]);
        __syncthreads();
    }
    mx = red[0];
    __syncthreads();

    float sum = 0.f;
    #pragma unroll
    for (int j = 0; j < 8; j++) { v[j] = expf(v[j] - mx); sum += v[j]; }
    red[tid] = sum; __syncthreads();
    for (int s = 128; s > 0; s >>= 1) {
        if (tid < s) red[tid] += red[tid + s];
        __syncthreads();
    }
    const float inv = 1.f / red[0];

    #pragma unroll
    for (int j = 0; j < 8; j++)
        out[65536 + b * S_SZ + j * 256 + tid] = v[j] * inv;
}

// ---------------------------------------------------------------------------
// Kernel 4a: wctx partials, split over S for occupancy.
// ---------------------------------------------------------------------------
__global__ __launch_bounds__(256) void wctx_part_kernel(
    const float* __restrict__ ctx, const float* __restrict__ out)
{
    __shared__ float w_s[256];
    const int b = blockIdx.x, sc = blockIdx.y, dc = blockIdx.z, tid = threadIdx.x;
    w_s[tid] = out[65536 + b * S_SZ + sc * 256 + tid];
    __syncthreads();

    const int d = dc * 256 + tid;
    const float* C = ctx + (size_t)b * S_SZ * D_SZ + (size_t)(sc * 256) * D_SZ + d;
    float acc = 0.f;
    #pragma unroll 8
    for (int s = 0; s < 256; s++)
        acc += w_s[s] * C[(size_t)s * D_SZ];
    g_part[((b * 8 + sc) << 10) + d] = acc;
}

// Kernel 4b: reduce 8 partials (fixed order -> deterministic)
__global__ __launch_bounds__(256) void wctx_reduce_kernel(float* __restrict__ out)
{
    const int b = blockIdx.x, dc = blockIdx.y, tid = threadIdx.x;
    const int d = dc * 256 + tid;
    float a = 0.f;
    #pragma unroll
    for (int sc = 0; sc < 8; sc++) a += g_part[((b * 8 + sc) << 10) + d];
    out[32768 + b * D_SZ + d] = a;
}

// ---------------------------------------------------------------------------
// Kernel 5: h_tilde[b,e] = tanh( [wc, input] @ W_out[e,:] )
// ---------------------------------------------------------------------------
__global__ __launch_bounds__(128) void htilde_kernel(
    const float* __restrict__ input,
    const float* __restrict__ W_out,
    float* __restrict__ out)
{
    __shared__ float x_s[2 * D_SZ];
    __shared__ float Ws[128][33];
    const int tid = threadIdx.x, chunk = blockIdx.x, b = blockIdx.y;

    for (int i = tid; i < 2 * D_SZ; i += 128)
        x_s[i] = (i < D_SZ) ? out[32768 + b * D_SZ + i]
                            : input[b * D_SZ + (i - D_SZ)];
    const int row = chunk * 128 + tid;
    float acc = 0.f;
    for (int k0 = 0; k0 < 2 * D_SZ; k0 += 32) {
        __syncthreads();
        for (int i = tid; i < 128 * 32; i += 128) {
            int d = i >> 5, k = i & 31;
            Ws[d][k] = W_out[(size_t)(chunk * 128 + d) * (2 * D_SZ) + k0 + k];
        }
        __syncthreads();
        #pragma unroll
        for (int k = 0; k < 32; k++) acc += x_s[k0 + k] * Ws[tid][k];
    }
    out[b * D_SZ + row] = tanhf(acc);
}

// ---------------------------------------------------------------------------
extern "C" void kernel_launch(void* const* d_in, const int* in_sizes, int n_in,
                              void* d_out, int out_size)
{
    const float* input   = (const float*)d_in[0];   // (32,1024)
    const float* context = (const float*)d_in[1];   // (32,2048,1024)
    const float* W_in    = (const float*)d_in[2];   // (1024,1024)
    const float* W_c     = (const float*)d_in[3];   // (1024,1024)
    const float* b_c     = (const float*)d_in[4];   // (1024)
    const float* W_v     = (const float*)d_in[5];   // (1024)
    const float* W_out   = (const float*)d_in[6];   // (1024,2048)
    float* out = (float*)d_out;

    cudaFuncSetAttribute(score_kernel,
                         cudaFuncAttributeMaxDynamicSharedMemorySize, SMEM_SCORE);

    prep_ctx_kernel  <<< 32768,          256 >>> (context);
    prep_wc_kernel   <<< 1024,           256 >>> (W_c);
    target_kernel    <<< dim3(8, 32),    128 >>> (input, W_in, b_c);
    score_kernel     <<< 512,            256, SMEM_SCORE >>> (W_v);
    softmax_kernel   <<< 32,             256 >>> (out);
    wctx_part_kernel <<< dim3(32, 8, 4), 256 >>> (context, out);
    wctx_reduce_kernel<<< dim3(32, 4),   256 >>> (out);
    htilde_kernel    <<< dim3(8, 32),    128 >>> (input, W_out, out);
}

// round 4
// speedup vs baseline: 2.2182x; 1.0566x over previous
#include <cuda_runtime.h>
#include <cuda_bf16.h>
#include <math.h>
#include <cstdint>

// ---------------------------------------------------------------------------
// MLPAttention: mma.sync bf16-split pipeline (sm_100 base target).
// B=32, S=2048, D=1024.
// out: [0,32768) h_tilde | [32768,65536) weighted_context | [65536,131072) attn_w
// ---------------------------------------------------------------------------

#define B_SZ   32
#define S_SZ   2048
#define D_SZ   1024
#define R_SZ   (B_SZ * S_SZ)

// Scratch (module statics: no runtime allocation)
__device__ float g_target[B_SZ * D_SZ];          // input @ W_in^T + b_c
__device__ float g_scores[R_SZ];                 // pre-softmax scores
__device__ float g_part[B_SZ * 8 * D_SZ];        // wctx split-S partials
// Fragment-ordered bf16 hi/lo planes.
// A (context): blocks [rt(512)][ks(64)][mt(8)] of [lane(32)]x16B
__device__ uint4 g_AH[(size_t)R_SZ * D_SZ / 8];  // 128MB
__device__ uint4 g_AL[(size_t)R_SZ * D_SZ / 8];  // 128MB
// B (W_c): blocks [dc(8)][ks(64)][nt(16)] of [lane(32)]x8B
__device__ uint2 g_BH[(size_t)D_SZ * D_SZ / 4];  // 2MB
__device__ uint2 g_BL[(size_t)D_SZ * D_SZ / 4];  // 2MB

// ---------------------------------------------------------------------------
// helpers
// ---------------------------------------------------------------------------
__device__ __forceinline__ uint32_t smem_u32(const void* p) {
    uint32_t a;
    asm("{ .reg .u64 t; cvta.to.shared.u64 t, %1; cvt.u32.u64 %0, t; }" : "=r"(a) : "l"(p));
    return a;
}

// rn hi/lo split: (a,b) -> packed bf16x2 hi (lo16=a, hi16=b) and lo residuals
__device__ __forceinline__ uint32_t split2(float a, float b, uint32_t& lo) {
    uint32_t h;
    asm("cvt.rn.bf16x2.f32 %0, %1, %2;" : "=r"(h) : "f"(b), "f"(a));
    float ah = __uint_as_float(h << 16);
    float bh = __uint_as_float(h & 0xFFFF0000u);
    float al = a - ah, bl = b - bh;
    uint32_t l;
    asm("cvt.rn.bf16x2.f32 %0, %1, %2;" : "=r"(l) : "f"(bl), "f"(al));
    lo = l;
    return h;
}

#define MMA_BF16(c, a, b)                                                       \
    asm volatile("mma.sync.aligned.m16n8k16.row.col.f32.bf16.bf16.f32 "         \
        "{%0,%1,%2,%3}, {%4,%5,%6,%7}, {%8,%9}, {%0,%1,%2,%3};"                 \
        : "+f"((c)[0]), "+f"((c)[1]), "+f"((c)[2]), "+f"((c)[3])                \
        : "r"((a).x), "r"((a).y), "r"((a).z), "r"((a).w),                       \
          "r"((b).x), "r"((b).y))

#define CP16(d, s)                                                              \
    asm volatile("cp.async.cg.shared.global [%0], [%1], 16;"                    \
                 :: "r"(d), "l"(s) : "memory")

// ---------------------------------------------------------------------------
// Kernel 0a: split context into bf16 hi/lo planes in A-fragment order.
// ---------------------------------------------------------------------------
__global__ __launch_bounds__(256) void prep_ctx_kernel(const float* __restrict__ ctx)
{
    const int task  = blockIdx.x * 8 + (threadIdx.x >> 5);
    const int lane  = threadIdx.x & 31;
    const int mtile = task >> 6;          // 0..4095 (16-row tiles)
    const int ks    = task & 63;          // 16-wide k step

    const int  r0 = mtile * 16 + (lane >> 2);
    const int  kb = ks * 16 + (lane & 3) * 2;
    const float* p0 = ctx + (size_t)r0 * D_SZ + kb;
    const float* p1 = ctx + (size_t)(r0 + 8) * D_SZ + kb;

    float2 f00 = *(const float2*)(p0);
    float2 f10 = *(const float2*)(p1);
    float2 f02 = *(const float2*)(p0 + 8);
    float2 f12 = *(const float2*)(p1 + 8);

    uint4 h, l;
    h.x = split2(f00.x, f00.y, l.x);
    h.y = split2(f10.x, f10.y, l.y);
    h.z = split2(f02.x, f02.y, l.z);
    h.w = split2(f12.x, f12.y, l.w);

    const int rt = mtile >> 3, mt = mtile & 7;
    const size_t blk = ((size_t)rt * 64 + ks) * 8 + mt;
    g_AH[blk * 32 + lane] = h;
    g_AL[blk * 32 + lane] = l;
}

// ---------------------------------------------------------------------------
// Kernel 0b: split W_c into bf16 hi/lo planes in B-fragment order.
// ---------------------------------------------------------------------------
__global__ __launch_bounds__(256) void prep_wc_kernel(const float* __restrict__ Wc)
{
    const int task  = blockIdx.x * 8 + (threadIdx.x >> 5);
    const int lane  = threadIdx.x & 31;
    const int ntile = task >> 6;          // 0..127 (8-col tiles)
    const int ks    = task & 63;

    const int n  = ntile * 8 + (lane >> 2);
    const int kb = ks * 16 + (lane & 3) * 2;
    float2 f0 = *(const float2*)(Wc + (size_t)n * D_SZ + kb);
    float2 f2 = *(const float2*)(Wc + (size_t)n * D_SZ + kb + 8);

    uint2 h, l;
    h.x = split2(f0.x, f0.y, l.x);
    h.y = split2(f2.x, f2.y, l.y);

    const int dc = ntile >> 4, nt = ntile & 15;
    const size_t blk = ((size_t)dc * 64 + ks) * 16 + nt;
    g_BH[blk * 32 + lane] = h;
    g_BL[blk * 32 + lane] = l;
}

// ---------------------------------------------------------------------------
// Kernel 1: target[b,e] = input[b,:] @ W_in[e,:] + b_c[e]
// ---------------------------------------------------------------------------
__global__ __launch_bounds__(128) void target_kernel(
    const float* __restrict__ input,
    const float* __restrict__ W_in,
    const float* __restrict__ b_c)
{
    __shared__ float x_s[D_SZ];
    __shared__ float Ws[128][33];
    const int tid = threadIdx.x, chunk = blockIdx.x, b = blockIdx.y;

    for (int i = tid; i < D_SZ; i += 128) x_s[i] = input[b * D_SZ + i];
    const int row = chunk * 128 + tid;
    float acc = 0.f;
    for (int k0 = 0; k0 < D_SZ; k0 += 32) {
        __syncthreads();
        for (int i = tid; i < 128 * 32; i += 128) {
            int d = i >> 5, k = i & 31;
            Ws[d][k] = W_in[(chunk * 128 + d) * D_SZ + k0 + k];
        }
        __syncthreads();
        #pragma unroll
        for (int k = 0; k < 32; k++) acc += x_s[k0 + k] * Ws[tid][k];
    }
    g_target[b * D_SZ + row] = acc + b_c[row];
}

// ---------------------------------------------------------------------------
// Kernel 2 (dominant): mma.sync bf16-split GEMM + tanh + W_v reduce -> scores.
// One CTA per 128 context rows (grid 512), 256 threads (8 warps).
// Warp grid 4(m) x 2(n): warp tile 32 x 64.
// Pipeline: 2 stages x 64KB (k-chunk 64), 128 iterations, one sync per iter,
// 192 warp-MMAs per iteration (2x R3 work per sync, half the syncs).
// ---------------------------------------------------------------------------
#define STAGES      2
#define STAGE_BYTES 65536            // AH 16K | AL 16K | BH 16K | BL 16K
#define TGT_OFF     (STAGES * STAGE_BYTES)
#define WV_OFF      (TGT_OFF + 4096)
#define SC_OFF      (WV_OFF + 4096)
#define SMEM_SCORE  (SC_OFF + 512)

__global__ __launch_bounds__(256, 1) void score_kernel(const float* __restrict__ Wv)
{
    extern __shared__ char smem[];
    const int tid  = threadIdx.x, wid = tid >> 5, lane = tid & 31;
    const int wm   = wid & 3, wn = wid >> 2;
    const int rt   = blockIdx.x;
    const int r0   = rt * 128, b = r0 >> 11;

    float* tgt_s = (float*)(smem + TGT_OFF);
    float* wv_s  = (float*)(smem + WV_OFF);
    float* sc_s  = (float*)(smem + SC_OFF);
    for (int i = tid; i < D_SZ; i += 256) {
        tgt_s[i] = g_target[b * D_SZ + i];
        wv_s[i]  = Wv[i];
    }

    const uint32_t sb = smem_u32(smem);

    // issue one 64KB stage (k-chunk of 64 = 4 ks blocks, contiguous 16KB/plane)
    auto issue = [&](int it) {
        const int kc = it & 15, dc = it >> 4, p = it & 1;
        const size_t aoff = ((size_t)rt * 64 + kc * 4) * 4096 + tid * 16;
        const size_t boff = ((size_t)dc * 64 + kc * 4) * 4096 + tid * 16;
        const char* sAH = (const char*)g_AH + aoff;
        const char* sAL = (const char*)g_AL + aoff;
        const char* sBH = (const char*)g_BH + boff;
        const char* sBL = (const char*)g_BL + boff;
        const uint32_t d = sb + p * STAGE_BYTES + tid * 16;
        #pragma unroll
        for (int r = 0; r < 4; r++) {
            CP16(d + r * 4096,         sAH + r * 4096);
            CP16(d + 16384 + r * 4096, sAL + r * 4096);
            CP16(d + 32768 + r * 4096, sBH + r * 4096);
            CP16(d + 49152 + r * 4096, sBL + r * 4096);
        }
        asm volatile("cp.async.commit_group;" ::: "memory");
    };

    issue(0);

    float c[2][8][4];
    float acc[2][2] = {{0.f, 0.f}, {0.f, 0.f}};

    for (int i = 0; i < 128; i++) {
        if ((i & 15) == 0) {
            #pragma unroll
            for (int m = 0; m < 2; m++)
                #pragma unroll
                for (int n = 0; n < 8; n++)
                    #pragma unroll
                    for (int q = 0; q < 4; q++) c[m][n][q] = 0.f;
        }

        asm volatile("cp.async.wait_group 0;" ::: "memory");
        __syncthreads();                 // data visible + all warps done with other buf
        if (i + 1 < 128) issue(i + 1);   // overlaps compute below

        const char* st = smem + (i & 1) * STAGE_BYTES;
        #pragma unroll
        for (int ks = 0; ks < 4; ks++) {
            uint4 aH[2], aL[2];
            #pragma unroll
            for (int m = 0; m < 2; m++) {
                const int mt = wm * 2 + m;
                aH[m] = *(const uint4*)(st +         ((ks * 8 + mt) * 32 + lane) * 16);
                aL[m] = *(const uint4*)(st + 16384 + ((ks * 8 + mt) * 32 + lane) * 16);
            }
            #pragma unroll
            for (int n = 0; n < 8; n++) {
                const int nt = wn * 8 + n;
                uint2 bH = *(const uint2*)(st + 32768 + ((ks * 16 + nt) * 32 + lane) * 8);
                uint2 bL = *(const uint2*)(st + 49152 + ((ks * 16 + nt) * 32 + lane) * 8);
                #pragma unroll
                for (int m = 0; m < 2; m++) {
                    MMA_BF16(c[m][n], aH[m], bH);
                    MMA_BF16(c[m][n], aH[m], bL);
                    MMA_BF16(c[m][n], aL[m], bH);
                }
            }
        }

        if ((i & 15) == 15) {
            const int dc = i >> 4;
            const int d0 = dc * 128 + wn * 64;
            #pragma unroll
            for (int m = 0; m < 2; m++) {
                #pragma unroll
                for (int n = 0; n < 8; n++) {
                    const int col = d0 + n * 8 + (lane & 3) * 2;
                    const float w0 = wv_s[col], w1 = wv_s[col + 1];
                    const float t0 = tgt_s[col], t1 = tgt_s[col + 1];
                    acc[m][0] += w0 * tanhf(t0 + c[m][n][0]) + w1 * tanhf(t1 + c[m][n][1]);
                    acc[m][1] += w0 * tanhf(t0 + c[m][n][2]) + w1 * tanhf(t1 + c[m][n][3]);
                }
            }
        }
    }

    // reduce the 4 lanes sharing each output row
    #pragma unroll
    for (int m = 0; m < 2; m++)
        #pragma unroll
        for (int h = 0; h < 2; h++) {
            acc[m][h] += __shfl_xor_sync(0xffffffffu, acc[m][h], 1);
            acc[m][h] += __shfl_xor_sync(0xffffffffu, acc[m][h], 2);
        }

    if (wn == 0 && (lane & 3) == 0) {
        #pragma unroll
        for (int m = 0; m < 2; m++)
            #pragma unroll
            for (int h = 0; h < 2; h++)
                sc_s[wm * 32 + m * 16 + h * 8 + (lane >> 2)] = acc[m][h];
    }
    __syncthreads();
    if (wn == 1 && (lane & 3) == 0) {
        #pragma unroll
        for (int m = 0; m < 2; m++)
            #pragma unroll
            for (int h = 0; h < 2; h++)
                sc_s[wm * 32 + m * 16 + h * 8 + (lane >> 2)] += acc[m][h];
    }
    __syncthreads();
    if (tid < 128) g_scores[r0 + tid] = sc_s[tid];
}

// ---------------------------------------------------------------------------
// Kernel 3: softmax over S per batch.
// ---------------------------------------------------------------------------
__global__ __launch_bounds__(256) void softmax_kernel(float* __restrict__ out)
{
    const int b = blockIdx.x, tid = threadIdx.x;
    __shared__ float red[256];

    float v[8];
    float mx = -1e30f;
    #pragma unroll
    for (int j = 0; j < 8; j++) {
        v[j] = g_scores[b * S_SZ + j * 256 + tid];
        mx = fmaxf(mx, v[j]);
    }
    red[tid] = mx; __syncthreads();
    for (int s = 128; s > 0; s >>= 1) {
        if (tid < s) red[tid] = fmaxf(red[tid], red[tid + s]);
        __syncthreads();
    }
    mx = red[0];
    __syncthreads();

    float sum = 0.f;
    #pragma unroll
    for (int j = 0; j < 8; j++) { v[j] = expf(v[j] - mx); sum += v[j]; }
    red[tid] = sum; __syncthreads();
    for (int s = 128; s > 0; s >>= 1) {
        if (tid < s) red[tid] += red[tid + s];
        __syncthreads();
    }
    const float inv = 1.f / red[0];

    #pragma unroll
    for (int j = 0; j < 8; j++)
        out[65536 + b * S_SZ + j * 256 + tid] = v[j] * inv;
}

// ---------------------------------------------------------------------------
// Kernel 4a: wctx partials, split over S.
// ---------------------------------------------------------------------------
__global__ __launch_bounds__(256) void wctx_part_kernel(
    const float* __restrict__ ctx, const float* __restrict__ out)
{
    __shared__ float w_s[256];
    const int b = blockIdx.x, sc = blockIdx.y, dc = blockIdx.z, tid = threadIdx.x;
    w_s[tid] = out[65536 + b * S_SZ + sc * 256 + tid];
    __syncthreads();

    const int d = dc * 256 + tid;
    const float* C = ctx + (size_t)b * S_SZ * D_SZ + (size_t)(sc * 256) * D_SZ + d;
    float acc = 0.f;
    #pragma unroll 8
    for (int s = 0; s < 256; s++)
        acc += w_s[s] * C[(size_t)s * D_SZ];
    g_part[((b * 8 + sc) << 10) + d] = acc;
}

// Kernel 4b: reduce 8 partials (fixed order -> deterministic)
__global__ __launch_bounds__(256) void wctx_reduce_kernel(float* __restrict__ out)
{
    const int b = blockIdx.x, dc = blockIdx.y, tid = threadIdx.x;
    const int d = dc * 256 + tid;
    float a = 0.f;
    #pragma unroll
    for (int sc = 0; sc < 8; sc++) a += g_part[((b * 8 + sc) << 10) + d];
    out[32768 + b * D_SZ + d] = a;
}

// ---------------------------------------------------------------------------
// Kernel 5: h_tilde[b,e] = tanh( [wc, input] @ W_out[e,:] )
// ---------------------------------------------------------------------------
__global__ __launch_bounds__(128) void htilde_kernel(
    const float* __restrict__ input,
    const float* __restrict__ W_out,
    float* __restrict__ out)
{
    __shared__ float x_s[2 * D_SZ];
    __shared__ float Ws[128][33];
    const int tid = threadIdx.x, chunk = blockIdx.x, b = blockIdx.y;

    for (int i = tid; i < 2 * D_SZ; i += 128)
        x_s[i] = (i < D_SZ) ? out[32768 + b * D_SZ + i]
                            : input[b * D_SZ + (i - D_SZ)];
    const int row = chunk * 128 + tid;
    float acc = 0.f;
    for (int k0 = 0; k0 < 2 * D_SZ; k0 += 32) {
        __syncthreads();
        for (int i = tid; i < 128 * 32; i += 128) {
            int d = i >> 5, k = i & 31;
            Ws[d][k] = W_out[(size_t)(chunk * 128 + d) * (2 * D_SZ) + k0 + k];
        }
        __syncthreads();
        #pragma unroll
        for (int k = 0; k < 32; k++) acc += x_s[k0 + k] * Ws[tid][k];
    }
    out[b * D_SZ + row] = tanhf(acc);
}

// ---------------------------------------------------------------------------
extern "C" void kernel_launch(void* const* d_in, const int* in_sizes, int n_in,
                              void* d_out, int out_size)
{
    const float* input   = (const float*)d_in[0];
    const float* context = (const float*)d_in[1];
    const float* W_in    = (const float*)d_in[2];
    const float* W_c     = (const float*)d_in[3];
    const float* b_c     = (const float*)d_in[4];
    const float* W_v     = (const float*)d_in[5];
    const float* W_out   = (const float*)d_in[6];
    float* out = (float*)d_out;

    cudaFuncSetAttribute(score_kernel,
                         cudaFuncAttributeMaxDynamicSharedMemorySize, SMEM_SCORE);

    prep_ctx_kernel  <<< 32768,          256 >>> (context);
    prep_wc_kernel   <<< 1024,           256 >>> (W_c);
    target_kernel    <<< dim3(8, 32),    128 >>> (input, W_in, b_c);
    score_kernel     <<< 512,            256, SMEM_SCORE >>> (W_v);
    softmax_kernel   <<< 32,             256 >>> (out);
    wctx_part_kernel <<< dim3(32, 8, 4), 256 >>> (context, out);
    wctx_reduce_kernel<<< dim3(32, 4),   256 >>> (out);
    htilde_kernel    <<< dim3(8, 32),    128 >>> (input, W_out, out);
}

// round 6
// speedup vs baseline: 2.3714x; 1.0691x over previous
#include <cuda_runtime.h>
#include <cuda_bf16.h>
#include <math.h>
#include <cstdint>

// ---------------------------------------------------------------------------
// MLPAttention: mma.sync bf16-split pipeline (sm_100 base target).
// B=32, S=2048, D=1024.
// out: [0,32768) h_tilde | [32768,65536) weighted_context | [65536,131072) attn_w
// R6: d-split score kernel (2 CTAs per r-tile, each does 512 d-cols with FULL k
//     -> tanh is exact; partial scores sum linearly). 1024 CTAs, 98.8% wave eff.
//     3-stage cp.async pipeline with issue-before-wait.
// ---------------------------------------------------------------------------

#define B_SZ   32
#define S_SZ   2048
#define D_SZ   1024
#define R_SZ   (B_SZ * S_SZ)

// Scratch (module statics: no runtime allocation)
__device__ float g_target[B_SZ * D_SZ];          // input @ W_in^T + b_c
__device__ float g_spart[2 * R_SZ];              // d-half partial scores
__device__ float g_part[B_SZ * 8 * D_SZ];        // wctx split-S partials
// Fragment-ordered bf16 hi/lo planes.
// A (context): blocks [rt(512)][ks(64)][mt(8)] of [lane(32)]x16B
__device__ uint4 g_AH[(size_t)R_SZ * D_SZ / 8];  // 128MB
__device__ uint4 g_AL[(size_t)R_SZ * D_SZ / 8];  // 128MB
// B (W_c): blocks [dc(8)][ks(64)][nt(16)] of [lane(32)]x8B
__device__ uint2 g_BH[(size_t)D_SZ * D_SZ / 4];  // 2MB
__device__ uint2 g_BL[(size_t)D_SZ * D_SZ / 4];  // 2MB

// ---------------------------------------------------------------------------
// helpers
// ---------------------------------------------------------------------------
__device__ __forceinline__ uint32_t smem_u32(const void* p) {
    uint32_t a;
    asm("{ .reg .u64 t; cvta.to.shared.u64 t, %1; cvt.u32.u64 %0, t; }" : "=r"(a) : "l"(p));
    return a;
}

// rn hi/lo split: (a,b) -> packed bf16x2 hi (lo16=a, hi16=b) and lo residuals
__device__ __forceinline__ uint32_t split2(float a, float b, uint32_t& lo) {
    uint32_t h;
    asm("cvt.rn.bf16x2.f32 %0, %1, %2;" : "=r"(h) : "f"(b), "f"(a));
    float ah = __uint_as_float(h << 16);
    float bh = __uint_as_float(h & 0xFFFF0000u);
    float al = a - ah, bl = b - bh;
    uint32_t l;
    asm("cvt.rn.bf16x2.f32 %0, %1, %2;" : "=r"(l) : "f"(bl), "f"(al));
    lo = l;
    return h;
}

#define MMA_BF16(c, a, b)                                                       \
    asm volatile("mma.sync.aligned.m16n8k16.row.col.f32.bf16.bf16.f32 "         \
        "{%0,%1,%2,%3}, {%4,%5,%6,%7}, {%8,%9}, {%0,%1,%2,%3};"                 \
        : "+f"((c)[0]), "+f"((c)[1]), "+f"((c)[2]), "+f"((c)[3])                \
        : "r"((a).x), "r"((a).y), "r"((a).z), "r"((a).w),                       \
          "r"((b).x), "r"((b).y))

#define CP16(d, s)                                                              \
    asm volatile("cp.async.cg.shared.global [%0], [%1], 16;"                    \
                 :: "r"(d), "l"(s) : "memory")

// ---------------------------------------------------------------------------
// Kernel 0a: split context into bf16 hi/lo planes in A-fragment order.
// ---------------------------------------------------------------------------
__global__ __launch_bounds__(256) void prep_ctx_kernel(const float* __restrict__ ctx)
{
    const int task  = blockIdx.x * 8 + (threadIdx.x >> 5);
    const int lane  = threadIdx.x & 31;
    const int mtile = task >> 6;          // 0..4095 (16-row tiles)
    const int ks    = task & 63;          // 16-wide k step

    const int  r0 = mtile * 16 + (lane >> 2);
    const int  kb = ks * 16 + (lane & 3) * 2;
    const float* p0 = ctx + (size_t)r0 * D_SZ + kb;
    const float* p1 = ctx + (size_t)(r0 + 8) * D_SZ + kb;

    float2 f00 = *(const float2*)(p0);
    float2 f10 = *(const float2*)(p1);
    float2 f02 = *(const float2*)(p0 + 8);
    float2 f12 = *(const float2*)(p1 + 8);

    uint4 h, l;
    h.x = split2(f00.x, f00.y, l.x);
    h.y = split2(f10.x, f10.y, l.y);
    h.z = split2(f02.x, f02.y, l.z);
    h.w = split2(f12.x, f12.y, l.w);

    const int rt = mtile >> 3, mt = mtile & 7;
    const size_t blk = ((size_t)rt * 64 + ks) * 8 + mt;
    g_AH[blk * 32 + lane] = h;
    g_AL[blk * 32 + lane] = l;
}

// ---------------------------------------------------------------------------
// Kernel 0b: split W_c into bf16 hi/lo planes in B-fragment order.
// ---------------------------------------------------------------------------
__global__ __launch_bounds__(256) void prep_wc_kernel(const float* __restrict__ Wc)
{
    const int task  = blockIdx.x * 8 + (threadIdx.x >> 5);
    const int lane  = threadIdx.x & 31;
    const int ntile = task >> 6;          // 0..127 (8-col tiles)
    const int ks    = task & 63;

    const int n  = ntile * 8 + (lane >> 2);
    const int kb = ks * 16 + (lane & 3) * 2;
    float2 f0 = *(const float2*)(Wc + (size_t)n * D_SZ + kb);
    float2 f2 = *(const float2*)(Wc + (size_t)n * D_SZ + kb + 8);

    uint2 h, l;
    h.x = split2(f0.x, f0.y, l.x);
    h.y = split2(f2.x, f2.y, l.y);

    const int dc = ntile >> 4, nt = ntile & 15;
    const size_t blk = ((size_t)dc * 64 + ks) * 16 + nt;
    g_BH[blk * 32 + lane] = h;
    g_BL[blk * 32 + lane] = l;
}

// ---------------------------------------------------------------------------
// Kernel 1: target[b,e] = input[b,:] @ W_in[e,:] + b_c[e]
// ---------------------------------------------------------------------------
__global__ __launch_bounds__(128) void target_kernel(
    const float* __restrict__ input,
    const float* __restrict__ W_in,
    const float* __restrict__ b_c)
{
    __shared__ float x_s[D_SZ];
    __shared__ float Ws[128][33];
    const int tid = threadIdx.x, chunk = blockIdx.x, b = blockIdx.y;

    for (int i = tid; i < D_SZ; i += 128) x_s[i] = input[b * D_SZ + i];
    const int row = chunk * 128 + tid;
    float acc = 0.f;
    for (int k0 = 0; k0 < D_SZ; k0 += 32) {
        __syncthreads();
        for (int i = tid; i < 128 * 32; i += 128) {
            int d = i >> 5, k = i & 31;
            Ws[d][k] = W_in[(chunk * 128 + d) * D_SZ + k0 + k];
        }
        __syncthreads();
        #pragma unroll
        for (int k = 0; k < 32; k++) acc += x_s[k0 + k] * Ws[tid][k];
    }
    g_target[b * D_SZ + row] = acc + b_c[row];
}

// ---------------------------------------------------------------------------
// Kernel 2 (dominant): mma.sync bf16-split GEMM + tanh + W_v reduce -> scores.
// Grid (512 r-tiles, 2 d-halves), 256 threads (8 warps), 1 CTA/SM.
// Each CTA: 4 d-chunks (within its 512-wide d-half) x 16 k-iters (FULL k).
// tanh sees the complete k-sum -> exact; d-half partial scores sum linearly.
// 3-stage x 64KB cp.async pipeline; issue(i+2) before wait_group.
// ---------------------------------------------------------------------------
#define STAGES      3
#define STAGE_BYTES 65536            // AH 16K | AL 16K | BH 16K | BL 16K
#define TGT_OFF     (STAGES * STAGE_BYTES)
#define WV_OFF      (TGT_OFF + 4096)
#define SC_OFF      (WV_OFF + 4096)
#define SMEM_SCORE  (SC_OFF + 512)

__global__ __launch_bounds__(256, 1) void score_kernel(const float* __restrict__ Wv)
{
    extern __shared__ char smem[];
    const int tid   = threadIdx.x, wid = tid >> 5, lane = tid & 31;
    const int wm    = wid & 3, wn = wid >> 2;
    const int rt    = blockIdx.x;
    const int dhalf = blockIdx.y;
    const int r0    = rt * 128, b = r0 >> 11;

    float* tgt_s = (float*)(smem + TGT_OFF);
    float* wv_s  = (float*)(smem + WV_OFF);
    float* sc_s  = (float*)(smem + SC_OFF);
    for (int i = tid; i < D_SZ; i += 256) {
        tgt_s[i] = g_target[b * D_SZ + i];
        wv_s[i]  = Wv[i];
    }

    const uint32_t sb = smem_u32(smem);

    // one 64KB stage = 4 consecutive 16-wide ks blocks (4KB/plane each).
    // iteration it: kc = it & 15 (full k: 16 x 64), dc_local = it >> 4 (0..3)
    auto issue = [&](int it) {
        const int kc = it & 15, dc = dhalf * 4 + (it >> 4), p = it % 3;
        const size_t aoff = ((size_t)rt * 64 + kc * 4) * 4096 + tid * 16;
        const size_t boff = ((size_t)dc * 64 + kc * 4) * 4096 + tid * 16;
        const char* sAH = (const char*)g_AH + aoff;
        const char* sAL = (const char*)g_AL + aoff;
        const char* sBH = (const char*)g_BH + boff;
        const char* sBL = (const char*)g_BL + boff;
        const uint32_t d = sb + p * STAGE_BYTES + tid * 16;
        #pragma unroll
        for (int r = 0; r < 4; r++) {
            CP16(d + r * 4096,         sAH + r * 4096);
            CP16(d + 16384 + r * 4096, sAL + r * 4096);
            CP16(d + 32768 + r * 4096, sBH + r * 4096);
            CP16(d + 49152 + r * 4096, sBL + r * 4096);
        }
        asm volatile("cp.async.commit_group;" ::: "memory");
    };

    issue(0); issue(1);

    float c[2][8][4];
    float acc[2][2] = {{0.f, 0.f}, {0.f, 0.f}};

    for (int i = 0; i < 64; i++) {
        if ((i & 15) == 0) {
            #pragma unroll
            for (int m = 0; m < 2; m++)
                #pragma unroll
                for (int n = 0; n < 8; n++)
                    #pragma unroll
                    for (int q = 0; q < 4; q++) c[m][n][q] = 0.f;
        }

        // barrier first (stage (i+2)%3 == (i-1)%3 must be fully consumed),
        // then launch the next copy, THEN block on stage i readiness.
        __syncthreads();
        if (i + 2 < 64) {
            issue(i + 2);
            asm volatile("cp.async.wait_group 2;" ::: "memory");
        } else if (i == 62) {
            asm volatile("cp.async.wait_group 1;" ::: "memory");
        } else {
            asm volatile("cp.async.wait_group 0;" ::: "memory");
        }
        __syncthreads();                 // stage i visible to all warps

        const char* st = smem + (i % 3) * STAGE_BYTES;
        #pragma unroll
        for (int ks = 0; ks < 4; ks++) {
            uint4 aH[2], aL[2];
            #pragma unroll
            for (int m = 0; m < 2; m++) {
                const int mt = wm * 2 + m;
                aH[m] = *(const uint4*)(st +         ((ks * 8 + mt) * 32 + lane) * 16);
                aL[m] = *(const uint4*)(st + 16384 + ((ks * 8 + mt) * 32 + lane) * 16);
            }
            #pragma unroll
            for (int n = 0; n < 8; n++) {
                const int nt = wn * 8 + n;
                uint2 bH = *(const uint2*)(st + 32768 + ((ks * 16 + nt) * 32 + lane) * 8);
                uint2 bL = *(const uint2*)(st + 49152 + ((ks * 16 + nt) * 32 + lane) * 8);
                #pragma unroll
                for (int m = 0; m < 2; m++) {
                    MMA_BF16(c[m][n], aH[m], bH);
                    MMA_BF16(c[m][n], aH[m], bL);
                    MMA_BF16(c[m][n], aL[m], bH);
                }
            }
        }

        if ((i & 15) == 15) {
            const int dc = dhalf * 4 + (i >> 4);
            const int d0 = dc * 128 + wn * 64;
            #pragma unroll
            for (int m = 0; m < 2; m++) {
                #pragma unroll
                for (int n = 0; n < 8; n++) {
                    const int col = d0 + n * 8 + (lane & 3) * 2;
                    const float w0 = wv_s[col], w1 = wv_s[col + 1];
                    const float t0 = tgt_s[col], t1 = tgt_s[col + 1];
                    acc[m][0] += w0 * tanhf(t0 + c[m][n][0]) + w1 * tanhf(t1 + c[m][n][1]);
                    acc[m][1] += w0 * tanhf(t0 + c[m][n][2]) + w1 * tanhf(t1 + c[m][n][3]);
                }
            }
        }
    }

    // reduce the 4 lanes sharing each output row
    #pragma unroll
    for (int m = 0; m < 2; m++)
        #pragma unroll
        for (int h = 0; h < 2; h++) {
            acc[m][h] += __shfl_xor_sync(0xffffffffu, acc[m][h], 1);
            acc[m][h] += __shfl_xor_sync(0xffffffffu, acc[m][h], 2);
        }

    if (wn == 0 && (lane & 3) == 0) {
        #pragma unroll
        for (int m = 0; m < 2; m++)
            #pragma unroll
            for (int h = 0; h < 2; h++)
                sc_s[wm * 32 + m * 16 + h * 8 + (lane >> 2)] = acc[m][h];
    }
    __syncthreads();
    if (wn == 1 && (lane & 3) == 0) {
        #pragma unroll
        for (int m = 0; m < 2; m++)
            #pragma unroll
            for (int h = 0; h < 2; h++)
                sc_s[wm * 32 + m * 16 + h * 8 + (lane >> 2)] += acc[m][h];
    }
    __syncthreads();
    if (tid < 128) g_spart[dhalf * R_SZ + r0 + tid] = sc_s[tid];
}

// ---------------------------------------------------------------------------
// Kernel 3: softmax over S per batch (sums the 2 d-half partials).
// ---------------------------------------------------------------------------
__global__ __launch_bounds__(256) void softmax_kernel(float* __restrict__ out)
{
    const int b = blockIdx.x, tid = threadIdx.x;
    __shared__ float red[256];

    float v[8];
    float mx = -1e30f;
    #pragma unroll
    for (int j = 0; j < 8; j++) {
        const int idx = b * S_SZ + j * 256 + tid;
        v[j] = g_spart[idx] + g_spart[R_SZ + idx];
        mx = fmaxf(mx, v[j]);
    }
    red[tid] = mx; __syncthreads();
    for (int s = 128; s > 0; s >>= 1) {
        if (tid < s) red[tid] = fmaxf(red[tid], red[tid + s]);
        __syncthreads();
    }
    mx = red[0];
    __syncthreads();

    float sum = 0.f;
    #pragma unroll
    for (int j = 0; j < 8; j++) { v[j] = expf(v[j] - mx); sum += v[j]; }
    red[tid] = sum; __syncthreads();
    for (int s = 128; s > 0; s >>= 1) {
        if (tid < s) red[tid] += red[tid + s];
        __syncthreads();
    }
    const float inv = 1.f / red[0];

    #pragma unroll
    for (int j = 0; j < 8; j++)
        out[65536 + b * S_SZ + j * 256 + tid] = v[j] * inv;
}

// ---------------------------------------------------------------------------
// Kernel 4a: wctx partials, split over S.
// ---------------------------------------------------------------------------
__global__ __launch_bounds__(256) void wctx_part_kernel(
    const float* __restrict__ ctx, const float* __restrict__ out)
{
    __shared__ float w_s[256];
    const int b = blockIdx.x, sc = blockIdx.y, dc = blockIdx.z, tid = threadIdx.x;
    w_s[tid] = out[65536 + b * S_SZ + sc * 256 + tid];
    __syncthreads();

    const int d = dc * 256 + tid;
    const float* C = ctx + (size_t)b * S_SZ * D_SZ + (size_t)(sc * 256) * D_SZ + d;
    float acc = 0.f;
    #pragma unroll 8
    for (int s = 0; s < 256; s++)
        acc += w_s[s] * C[(size_t)s * D_SZ];
    g_part[((b * 8 + sc) << 10) + d] = acc;
}

// Kernel 4b: reduce 8 partials (fixed order -> deterministic)
__global__ __launch_bounds__(256) void wctx_reduce_kernel(float* __restrict__ out)
{
    const int b = blockIdx.x, dc = blockIdx.y, tid = threadIdx.x;
    const int d = dc * 256 + tid;
    float a = 0.f;
    #pragma unroll
    for (int sc = 0; sc < 8; sc++) a += g_part[((b * 8 + sc) << 10) + d];
    out[32768 + b * D_SZ + d] = a;
}

// ---------------------------------------------------------------------------
// Kernel 5: h_tilde[b,e] = tanh( [wc, input] @ W_out[e,:] )
// ---------------------------------------------------------------------------
__global__ __launch_bounds__(128) void htilde_kernel(
    const float* __restrict__ input,
    const float* __restrict__ W_out,
    float* __restrict__ out)
{
    __shared__ float x_s[2 * D_SZ];
    __shared__ float Ws[128][33];
    const int tid = threadIdx.x, chunk = blockIdx.x, b = blockIdx.y;

    for (int i = tid; i < 2 * D_SZ; i += 128)
        x_s[i] = (i < D_SZ) ? out[32768 + b * D_SZ + i]
                            : input[b * D_SZ + (i - D_SZ)];
    const int row = chunk * 128 + tid;
    float acc = 0.f;
    for (int k0 = 0; k0 < 2 * D_SZ; k0 += 32) {
        __syncthreads();
        for (int i = tid; i < 128 * 32; i += 128) {
            int d = i >> 5, k = i & 31;
            Ws[d][k] = W_out[(size_t)(chunk * 128 + d) * (2 * D_SZ) + k0 + k];
        }
        __syncthreads();
        #pragma unroll
        for (int k = 0; k < 32; k++) acc += x_s[k0 + k] * Ws[tid][k];
    }
    out[b * D_SZ + row] = tanhf(acc);
}

// ---------------------------------------------------------------------------
extern "C" void kernel_launch(void* const* d_in, const int* in_sizes, int n_in,
                              void* d_out, int out_size)
{
    const float* input   = (const float*)d_in[0];
    const float* context = (const float*)d_in[1];
    const float* W_in    = (const float*)d_in[2];
    const float* W_c     = (const float*)d_in[3];
    const float* b_c     = (const float*)d_in[4];
    const float* W_v     = (const float*)d_in[5];
    const float* W_out   = (const float*)d_in[6];
    float* out = (float*)d_out;

    cudaFuncSetAttribute(score_kernel,
                         cudaFuncAttributeMaxDynamicSharedMemorySize, SMEM_SCORE);

    prep_ctx_kernel  <<< 32768,          256 >>> (context);
    prep_wc_kernel   <<< 1024,           256 >>> (W_c);
    target_kernel    <<< dim3(8, 32),    128 >>> (input, W_in, b_c);
    score_kernel     <<< dim3(512, 2),   256, SMEM_SCORE >>> (W_v);
    softmax_kernel   <<< 32,             256 >>> (out);
    wctx_part_kernel <<< dim3(32, 8, 4), 256 >>> (context, out);
    wctx_reduce_kernel<<< dim3(32, 4),   256 >>> (out);
    htilde_kernel    <<< dim3(8, 32),    128 >>> (input, W_out, out);
}

// round 7
// speedup vs baseline: 2.3912x; 1.0083x over previous
#include <cuda_runtime.h>
#include <cuda_bf16.h>
#include <math.h>
#include <cstdint>

// ---------------------------------------------------------------------------
// MLPAttention: mma.sync bf16-split pipeline (sm_100 base target).
// B=32, S=2048, D=1024.
// out: [0,32768) h_tilde | [32768,65536) weighted_context | [65536,131072) attn_w
// R7: one-sync CUTLASS-style mainloop + dhalf-major grid for A L2 reuse.
// ---------------------------------------------------------------------------

#define B_SZ   32
#define S_SZ   2048
#define D_SZ   1024
#define R_SZ   (B_SZ * S_SZ)

// Scratch (module statics: no runtime allocation)
__device__ float g_target[B_SZ * D_SZ];          // input @ W_in^T + b_c
__device__ float g_spart[2 * R_SZ];              // d-half partial scores
__device__ float g_part[B_SZ * 8 * D_SZ];        // wctx split-S partials
// Fragment-ordered bf16 hi/lo planes.
// A (context): blocks [rt(512)][ks(64)][mt(8)] of [lane(32)]x16B
__device__ uint4 g_AH[(size_t)R_SZ * D_SZ / 8];  // 128MB
__device__ uint4 g_AL[(size_t)R_SZ * D_SZ / 8];  // 128MB
// B (W_c): blocks [dc(8)][ks(64)][nt(16)] of [lane(32)]x8B
__device__ uint2 g_BH[(size_t)D_SZ * D_SZ / 4];  // 2MB
__device__ uint2 g_BL[(size_t)D_SZ * D_SZ / 4];  // 2MB

// ---------------------------------------------------------------------------
// helpers
// ---------------------------------------------------------------------------
__device__ __forceinline__ uint32_t smem_u32(const void* p) {
    uint32_t a;
    asm("{ .reg .u64 t; cvta.to.shared.u64 t, %1; cvt.u32.u64 %0, t; }" : "=r"(a) : "l"(p));
    return a;
}

// rn hi/lo split: (a,b) -> packed bf16x2 hi (lo16=a, hi16=b) and lo residuals
__device__ __forceinline__ uint32_t split2(float a, float b, uint32_t& lo) {
    uint32_t h;
    asm("cvt.rn.bf16x2.f32 %0, %1, %2;" : "=r"(h) : "f"(b), "f"(a));
    float ah = __uint_as_float(h << 16);
    float bh = __uint_as_float(h & 0xFFFF0000u);
    float al = a - ah, bl = b - bh;
    uint32_t l;
    asm("cvt.rn.bf16x2.f32 %0, %1, %2;" : "=r"(l) : "f"(bl), "f"(al));
    lo = l;
    return h;
}

#define MMA_BF16(c, a, b)                                                       \
    asm volatile("mma.sync.aligned.m16n8k16.row.col.f32.bf16.bf16.f32 "         \
        "{%0,%1,%2,%3}, {%4,%5,%6,%7}, {%8,%9}, {%0,%1,%2,%3};"                 \
        : "+f"((c)[0]), "+f"((c)[1]), "+f"((c)[2]), "+f"((c)[3])                \
        : "r"((a).x), "r"((a).y), "r"((a).z), "r"((a).w),                       \
          "r"((b).x), "r"((b).y))

#define CP16(d, s)                                                              \
    asm volatile("cp.async.cg.shared.global [%0], [%1], 16;"                    \
                 :: "r"(d), "l"(s) : "memory")

// ---------------------------------------------------------------------------
// Kernel 0a: split context into bf16 hi/lo planes in A-fragment order.
// ---------------------------------------------------------------------------
__global__ __launch_bounds__(256) void prep_ctx_kernel(const float* __restrict__ ctx)
{
    const int task  = blockIdx.x * 8 + (threadIdx.x >> 5);
    const int lane  = threadIdx.x & 31;
    const int mtile = task >> 6;          // 0..4095 (16-row tiles)
    const int ks    = task & 63;          // 16-wide k step

    const int  r0 = mtile * 16 + (lane >> 2);
    const int  kb = ks * 16 + (lane & 3) * 2;
    const float* p0 = ctx + (size_t)r0 * D_SZ + kb;
    const float* p1 = ctx + (size_t)(r0 + 8) * D_SZ + kb;

    float2 f00 = *(const float2*)(p0);
    float2 f10 = *(const float2*)(p1);
    float2 f02 = *(const float2*)(p0 + 8);
    float2 f12 = *(const float2*)(p1 + 8);

    uint4 h, l;
    h.x = split2(f00.x, f00.y, l.x);
    h.y = split2(f10.x, f10.y, l.y);
    h.z = split2(f02.x, f02.y, l.z);
    h.w = split2(f12.x, f12.y, l.w);

    const int rt = mtile >> 3, mt = mtile & 7;
    const size_t blk = ((size_t)rt * 64 + ks) * 8 + mt;
    g_AH[blk * 32 + lane] = h;
    g_AL[blk * 32 + lane] = l;
}

// ---------------------------------------------------------------------------
// Kernel 0b: split W_c into bf16 hi/lo planes in B-fragment order.
// ---------------------------------------------------------------------------
__global__ __launch_bounds__(256) void prep_wc_kernel(const float* __restrict__ Wc)
{
    const int task  = blockIdx.x * 8 + (threadIdx.x >> 5);
    const int lane  = threadIdx.x & 31;
    const int ntile = task >> 6;          // 0..127 (8-col tiles)
    const int ks    = task & 63;

    const int n  = ntile * 8 + (lane >> 2);
    const int kb = ks * 16 + (lane & 3) * 2;
    float2 f0 = *(const float2*)(Wc + (size_t)n * D_SZ + kb);
    float2 f2 = *(const float2*)(Wc + (size_t)n * D_SZ + kb + 8);

    uint2 h, l;
    h.x = split2(f0.x, f0.y, l.x);
    h.y = split2(f2.x, f2.y, l.y);

    const int dc = ntile >> 4, nt = ntile & 15;
    const size_t blk = ((size_t)dc * 64 + ks) * 16 + nt;
    g_BH[blk * 32 + lane] = h;
    g_BL[blk * 32 + lane] = l;
}

// ---------------------------------------------------------------------------
// Kernel 1: target[b,e] = input[b,:] @ W_in[e,:] + b_c[e]
// ---------------------------------------------------------------------------
__global__ __launch_bounds__(128) void target_kernel(
    const float* __restrict__ input,
    const float* __restrict__ W_in,
    const float* __restrict__ b_c)
{
    __shared__ float x_s[D_SZ];
    __shared__ float Ws[128][33];
    const int tid = threadIdx.x, chunk = blockIdx.x, b = blockIdx.y;

    for (int i = tid; i < D_SZ; i += 128) x_s[i] = input[b * D_SZ + i];
    const int row = chunk * 128 + tid;
    float acc = 0.f;
    for (int k0 = 0; k0 < D_SZ; k0 += 32) {
        __syncthreads();
        for (int i = tid; i < 128 * 32; i += 128) {
            int d = i >> 5, k = i & 31;
            Ws[d][k] = W_in[(chunk * 128 + d) * D_SZ + k0 + k];
        }
        __syncthreads();
        #pragma unroll
        for (int k = 0; k < 32; k++) acc += x_s[k0 + k] * Ws[tid][k];
    }
    g_target[b * D_SZ + row] = acc + b_c[row];
}

// ---------------------------------------------------------------------------
// Kernel 2 (dominant): mma.sync bf16-split GEMM + tanh + W_v reduce -> scores.
// Grid (2 d-halves [x, fastest -> dhalf pairs adjacent in launch order for A
// L2 reuse], 512 r-tiles [y]), 256 threads (8 warps), 1 CTA/SM.
// Each CTA: 4 d-chunks (within its 512-wide d-half) x 16 k-iters (FULL k).
// 3-stage x 64KB cp.async pipeline, ONE __syncthreads per iteration:
//   wait_group -> sync (stage ready & old stage consumed) -> issue(i+2) -> MMA.
// ---------------------------------------------------------------------------
#define STAGES      3
#define STAGE_BYTES 65536            // AH 16K | AL 16K | BH 16K | BL 16K
#define TGT_OFF     (STAGES * STAGE_BYTES)
#define WV_OFF      (TGT_OFF + 4096)
#define SC_OFF      (WV_OFF + 4096)
#define SMEM_SCORE  (SC_OFF + 512)

__global__ __launch_bounds__(256, 1) void score_kernel(const float* __restrict__ Wv)
{
    extern __shared__ char smem[];
    const int tid   = threadIdx.x, wid = tid >> 5, lane = tid & 31;
    const int wm    = wid & 3, wn = wid >> 2;
    const int dhalf = blockIdx.x;
    const int rt    = blockIdx.y;
    const int r0    = rt * 128, b = r0 >> 11;

    float* tgt_s = (float*)(smem + TGT_OFF);
    float* wv_s  = (float*)(smem + WV_OFF);
    float* sc_s  = (float*)(smem + SC_OFF);
    for (int i = tid; i < D_SZ; i += 256) {
        tgt_s[i] = g_target[b * D_SZ + i];
        wv_s[i]  = Wv[i];
    }

    const uint32_t sb = smem_u32(smem);

    // one 64KB stage = 4 consecutive 16-wide ks blocks (4KB/plane each).
    // iteration it: kc = it & 15 (full k), dc_local = it >> 4 (0..3)
    auto issue = [&](int it) {
        const int kc = it & 15, dc = dhalf * 4 + (it >> 4), p = it % 3;
        const size_t aoff = ((size_t)rt * 64 + kc * 4) * 4096 + tid * 16;
        const size_t boff = ((size_t)dc * 64 + kc * 4) * 4096 + tid * 16;
        const char* sAH = (const char*)g_AH + aoff;
        const char* sAL = (const char*)g_AL + aoff;
        const char* sBH = (const char*)g_BH + boff;
        const char* sBL = (const char*)g_BL + boff;
        const uint32_t d = sb + p * STAGE_BYTES + tid * 16;
        #pragma unroll
        for (int r = 0; r < 4; r++) {
            CP16(d + r * 4096,         sAH + r * 4096);
            CP16(d + 16384 + r * 4096, sAL + r * 4096);
            CP16(d + 32768 + r * 4096, sBH + r * 4096);
            CP16(d + 49152 + r * 4096, sBL + r * 4096);
        }
        asm volatile("cp.async.commit_group;" ::: "memory");
    };

    issue(0); issue(1);

    float c[2][8][4];
    float acc[2][2] = {{0.f, 0.f}, {0.f, 0.f}};

    for (int i = 0; i < 64; i++) {
        if ((i & 15) == 0) {
            #pragma unroll
            for (int m = 0; m < 2; m++)
                #pragma unroll
                for (int n = 0; n < 8; n++)
                    #pragma unroll
                    for (int q = 0; q < 4; q++) c[m][n][q] = 0.f;
        }

        // stage i ready (<=1 group pending; at the last iter require 0)
        if (i < 63) asm volatile("cp.async.wait_group 1;" ::: "memory");
        else        asm volatile("cp.async.wait_group 0;" ::: "memory");
        // single barrier: stage i visible to all warps AND stage (i+2)%3
        // (= (i-1)%3) fully consumed by all warps (they read it in iter i-1).
        __syncthreads();
        if (i + 2 < 64) issue(i + 2);    // overlaps the MMA work below

        const char* st = smem + (i % 3) * STAGE_BYTES;
        #pragma unroll
        for (int ks = 0; ks < 4; ks++) {
            uint4 aH[2], aL[2];
            #pragma unroll
            for (int m = 0; m < 2; m++) {
                const int mt = wm * 2 + m;
                aH[m] = *(const uint4*)(st +         ((ks * 8 + mt) * 32 + lane) * 16);
                aL[m] = *(const uint4*)(st + 16384 + ((ks * 8 + mt) * 32 + lane) * 16);
            }
            #pragma unroll
            for (int n = 0; n < 8; n++) {
                const int nt = wn * 8 + n;
                uint2 bH = *(const uint2*)(st + 32768 + ((ks * 16 + nt) * 32 + lane) * 8);
                uint2 bL = *(const uint2*)(st + 49152 + ((ks * 16 + nt) * 32 + lane) * 8);
                #pragma unroll
                for (int m = 0; m < 2; m++) {
                    MMA_BF16(c[m][n], aH[m], bH);
                    MMA_BF16(c[m][n], aH[m], bL);
                    MMA_BF16(c[m][n], aL[m], bH);
                }
            }
        }

        if ((i & 15) == 15) {
            const int dc = dhalf * 4 + (i >> 4);
            const int d0 = dc * 128 + wn * 64;
            #pragma unroll
            for (int m = 0; m < 2; m++) {
                #pragma unroll
                for (int n = 0; n < 8; n++) {
                    const int col = d0 + n * 8 + (lane & 3) * 2;
                    const float w0 = wv_s[col], w1 = wv_s[col + 1];
                    const float t0 = tgt_s[col], t1 = tgt_s[col + 1];
                    acc[m][0] += w0 * tanhf(t0 + c[m][n][0]) + w1 * tanhf(t1 + c[m][n][1]);
                    acc[m][1] += w0 * tanhf(t0 + c[m][n][2]) + w1 * tanhf(t1 + c[m][n][3]);
                }
            }
        }
    }

    // reduce the 4 lanes sharing each output row
    #pragma unroll
    for (int m = 0; m < 2; m++)
        #pragma unroll
        for (int h = 0; h < 2; h++) {
            acc[m][h] += __shfl_xor_sync(0xffffffffu, acc[m][h], 1);
            acc[m][h] += __shfl_xor_sync(0xffffffffu, acc[m][h], 2);
        }

    if (wn == 0 && (lane & 3) == 0) {
        #pragma unroll
        for (int m = 0; m < 2; m++)
            #pragma unroll
            for (int h = 0; h < 2; h++)
                sc_s[wm * 32 + m * 16 + h * 8 + (lane >> 2)] = acc[m][h];
    }
    __syncthreads();
    if (wn == 1 && (lane & 3) == 0) {
        #pragma unroll
        for (int m = 0; m < 2; m++)
            #pragma unroll
            for (int h = 0; h < 2; h++)
                sc_s[wm * 32 + m * 16 + h * 8 + (lane >> 2)] += acc[m][h];
    }
    __syncthreads();
    if (tid < 128) g_spart[dhalf * R_SZ + r0 + tid] = sc_s[tid];
}

// ---------------------------------------------------------------------------
// Kernel 3: softmax over S per batch (sums the 2 d-half partials).
// ---------------------------------------------------------------------------
__global__ __launch_bounds__(256) void softmax_kernel(float* __restrict__ out)
{
    const int b = blockIdx.x, tid = threadIdx.x;
    __shared__ float red[256];

    float v[8];
    float mx = -1e30f;
    #pragma unroll
    for (int j = 0; j < 8; j++) {
        const int idx = b * S_SZ + j * 256 + tid;
        v[j] = g_spart[idx] + g_spart[R_SZ + idx];
        mx = fmaxf(mx, v[j]);
    }
    red[tid] = mx; __syncthreads();
    for (int s = 128; s > 0; s >>= 1) {
        if (tid < s) red[tid] = fmaxf(red[tid], red[tid + s]);
        __syncthreads();
    }
    mx = red[0];
    __syncthreads();

    float sum = 0.f;
    #pragma unroll
    for (int j = 0; j < 8; j++) { v[j] = expf(v[j] - mx); sum += v[j]; }
    red[tid] = sum; __syncthreads();
    for (int s = 128; s > 0; s >>= 1) {
        if (tid < s) red[tid] += red[tid + s];
        __syncthreads();
    }
    const float inv = 1.f / red[0];

    #pragma unroll
    for (int j = 0; j < 8; j++)
        out[65536 + b * S_SZ + j * 256 + tid] = v[j] * inv;
}

// ---------------------------------------------------------------------------
// Kernel 4a: wctx partials, split over S.
// ---------------------------------------------------------------------------
__global__ __launch_bounds__(256) void wctx_part_kernel(
    const float* __restrict__ ctx, const float* __restrict__ out)
{
    __shared__ float w_s[256];
    const int b = blockIdx.x, sc = blockIdx.y, dc = blockIdx.z, tid = threadIdx.x;
    w_s[tid] = out[65536 + b * S_SZ + sc * 256 + tid];
    __syncthreads();

    const int d = dc * 256 + tid;
    const float* C = ctx + (size_t)b * S_SZ * D_SZ + (size_t)(sc * 256) * D_SZ + d;
    float acc = 0.f;
    #pragma unroll 8
    for (int s = 0; s < 256; s++)
        acc += w_s[s] * C[(size_t)s * D_SZ];
    g_part[((b * 8 + sc) << 10) + d] = acc;
}

// Kernel 4b: reduce 8 partials (fixed order -> deterministic)
__global__ __launch_bounds__(256) void wctx_reduce_kernel(float* __restrict__ out)
{
    const int b = blockIdx.x, dc = blockIdx.y, tid = threadIdx.x;
    const int d = dc * 256 + tid;
    float a = 0.f;
    #pragma unroll
    for (int sc = 0; sc < 8; sc++) a += g_part[((b * 8 + sc) << 10) + d];
    out[32768 + b * D_SZ + d] = a;
}

// ---------------------------------------------------------------------------
// Kernel 5: h_tilde[b,e] = tanh( [wc, input] @ W_out[e,:] )
// ---------------------------------------------------------------------------
__global__ __launch_bounds__(128) void htilde_kernel(
    const float* __restrict__ input,
    const float* __restrict__ W_out,
    float* __restrict__ out)
{
    __shared__ float x_s[2 * D_SZ];
    __shared__ float Ws[128][33];
    const int tid = threadIdx.x, chunk = blockIdx.x, b = blockIdx.y;

    for (int i = tid; i < 2 * D_SZ; i += 128)
        x_s[i] = (i < D_SZ) ? out[32768 + b * D_SZ + i]
                            : input[b * D_SZ + (i - D_SZ)];
    const int row = chunk * 128 + tid;
    float acc = 0.f;
    for (int k0 = 0; k0 < 2 * D_SZ; k0 += 32) {
        __syncthreads();
        for (int i = tid; i < 128 * 32; i += 128) {
            int d = i >> 5, k = i & 31;
            Ws[d][k] = W_out[(size_t)(chunk * 128 + d) * (2 * D_SZ) + k0 + k];
        }
        __syncthreads();
        #pragma unroll
        for (int k = 0; k < 32; k++) acc += x_s[k0 + k] * Ws[tid][k];
    }
    out[b * D_SZ + row] = tanhf(acc);
}

// ---------------------------------------------------------------------------
extern "C" void kernel_launch(void* const* d_in, const int* in_sizes, int n_in,
                              void* d_out, int out_size)
{
    const float* input   = (const float*)d_in[0];
    const float* context = (const float*)d_in[1];
    const float* W_in    = (const float*)d_in[2];
    const float* W_c     = (const float*)d_in[3];
    const float* b_c     = (const float*)d_in[4];
    const float* W_v     = (const float*)d_in[5];
    const float* W_out   = (const float*)d_in[6];
    float* out = (float*)d_out;

    cudaFuncSetAttribute(score_kernel,
                         cudaFuncAttributeMaxDynamicSharedMemorySize, SMEM_SCORE);

    prep_ctx_kernel  <<< 32768,          256 >>> (context);
    prep_wc_kernel   <<< 1024,           256 >>> (W_c);
    target_kernel    <<< dim3(8, 32),    128 >>> (input, W_in, b_c);
    score_kernel     <<< dim3(2, 512),   256, SMEM_SCORE >>> (W_v);
    softmax_kernel   <<< 32,             256 >>> (out);
    wctx_part_kernel <<< dim3(32, 8, 4), 256 >>> (context, out);
    wctx_reduce_kernel<<< dim3(32, 4),   256 >>> (out);
    htilde_kernel    <<< dim3(8, 32),    128 >>> (input, W_out, out);
}